// round 14
// baseline (speedup 1.0000x reference)
#include <cuda_runtime.h>
#include <cstdint>
typedef unsigned long long ull;

#define Bk 32
#define Sk 4096
#define Ik 64
#define Rk 1024
#define Ok 8

#define NB 128
#define BPB 8
#define JPB 32
#define RPB 80       // bytes per k-pair row in rP
#define STP 1026
#define SMEM_BYTES (JPB*STP*4)   // 131328; covers rP(40960)+red(2*8448)
#define SENT 0x7F800000u         // +inf: tanh output can never be inf

__device__ float g_pre[(size_t)Bk*Sk*Rk];
__device__ float g_rs [(size_t)Bk*Sk*Rk];
// 4 slots x [4 pb][32 pj][8 b][32 jl] floats; producer region = contiguous 1KB
__device__ float g_rbuf2[4*Bk*Rk];

__device__ __forceinline__ void fma2(ull& a, ull b, ull c) {
    asm("fma.rn.f32x2 %0, %1, %2, %0;" : "+l"(a) : "l"(b), "l"(c));
}
__device__ __forceinline__ float hsum2(ull a) {
    unsigned l, h; asm("mov.b64 {%0,%1}, %2;" : "=r"(l), "=r"(h) : "l"(a));
    return __uint_as_float(l) + __uint_as_float(h);
}

__global__ void reset_kernel() {   // sentinel-fill all 4 slots
    unsigned* p = (unsigned*)g_rbuf2;
    int i = blockIdx.x*blockDim.x + threadIdx.x;
    for (int k = i; k < 4*Bk*Rk; k += 128*256) p[k] = SENT;
}
__global__ void nop_kernel() {}

// ---- Phase 1: pre = x @ W_in^T ---------------------------------------------
__global__ void __launch_bounds__(256) pre_kernel(const float* __restrict__ x,
                                                  const float* __restrict__ Win)
{
    __shared__ __align__(16) float xs[32*68];
    size_t rowBase = (size_t)blockIdx.x*32;
    for (int idx = threadIdx.x; idx < 32*64; idx += 256)
        xs[(idx>>6)*68 + (idx&63)] = x[(rowBase + (idx>>6))*64 + (idx&63)];
    __syncthreads();
    for (int jj = 0; jj < 4; jj++) {
        int j = jj*256 + threadIdx.x;
        ull w[32];
        const ull* wp = (const ull*)(Win + (size_t)j*64);
#pragma unroll
        for (int q = 0; q < 32; q++) w[q] = wp[q];
#pragma unroll 1
        for (int r = 0; r < 32; r++) {
            const ull* xr = (const ull*)&xs[r*68];
            ull a = 0, b = 0, c = 0, d = 0;
#pragma unroll
            for (int q = 0; q < 32; q += 4) {
                fma2(a, w[q], xr[q]);     fma2(b, w[q+1], xr[q+1]);
                fma2(c, w[q+2], xr[q+2]); fma2(d, w[q+3], xr[q+3]);
            }
            g_pre[(rowBase + r)*Rk + j] = (hsum2(a)+hsum2(b))+(hsum2(c)+hsum2(d));
        }
    }
}

// ---------------------------------------------------------------------------
// Phase 2: persistent recurrence, ONE-HOP exchange.
// Producer (pb,pj) epilogue: refill slot (t+2)&3 with sentinel (relaxed),
// then st.release its r(t) region in slot t&3 — the data store IS the release.
// Consumer warp wid reads its 4 producer regions with relaxed v4 loads,
// retrying only vectors that still contain a sentinel word. No flags.
// ---------------------------------------------------------------------------
__global__ void __launch_bounds__(256, 1) esn_main(const float* __restrict__ Wres)
{
    extern __shared__ __align__(16) float sm[];
    char* smc = (char*)sm;
    const int tid = threadIdx.x, wid = tid >> 5, lane = tid & 31;
    const int pb = blockIdx.x >> 5, pj = blockIdx.x & 31;
    const int b0 = pb*BPB, j0 = pj*JPB;
    const int kp0 = wid*64;

    // stage W slice, pull this thread's 64 (even,odd) weight pairs into regs
    for (int jl = 0; jl < JPB; jl++) {
        const float* src = Wres + (size_t)(j0 + jl)*Rk;
        for (int k = tid; k < Rk; k += 256) sm[jl*STP + k] = src[k];
    }
    __syncthreads();
    ull w2[64];
    {
        const ull* ws = (const ull*)(sm + lane*STP);
#pragma unroll
        for (int u = 0; u < 64; u++) w2[u] = ws[kp0 + u];
    }
    __syncthreads();
    // zero rP (t=0 uses r(-1)=0 and skips the exchange)
    for (int i = tid; i < (512*RPB)/4; i += 256) ((float*)smc)[i] = 0.f;
    __syncthreads();

    char* rP   = smc;                              // [512 kp][RPB] warp-private
    char* redb = smc + 512*RPB;                    // 2 x [64][33] floats
    // producer store addr (floats): region (slot,pb,pj), word (wid=b, lane=jl)
    const size_t myreg = ((size_t)pb*32 + pj)*256 + (size_t)wid*32 + lane;

    for (int t = 0; t < Sk; t++) {
        float preval = g_pre[((size_t)(b0 + wid)*Sk + t)*Rk + (j0 + lane)];

        if (t > 0) {
            // ---- one-hop poll+load: 8 relaxed v4 loads, per-vector retry
            const int slot = (t - 1) & 3;
            const float4* rb2 = (const float4*)g_rbuf2;
            size_t rbase[4];
#pragma unroll
            for (int q = 0; q < 4; q++)
                rbase[q] = ((size_t)slot*Bk*Rk)/4 + ((size_t)pb*32 + (wid*4 + q))*64;
            float4 v[8];
            unsigned miss = 0xFFu;
            do {
#pragma unroll
                for (int i = 0; i < 8; i++) if ((miss >> i) & 1u) {
                    const float4* p = rb2 + rbase[i>>1] + ((i&1)*32 + lane);
                    asm volatile("ld.relaxed.gpu.global.v4.f32 {%0,%1,%2,%3}, [%4];"
                                 : "=f"(v[i].x), "=f"(v[i].y), "=f"(v[i].z), "=f"(v[i].w)
                                 : "l"(p) : "memory");
                    unsigned bad = (__float_as_uint(v[i].x) == SENT) |
                                   (__float_as_uint(v[i].y) == SENT) |
                                   (__float_as_uint(v[i].z) == SENT) |
                                   (__float_as_uint(v[i].w) == SENT);
                    if (!bad) miss &= ~(1u << i);
                }
            } while (__any_sync(~0u, miss != 0u));
            // ---- stage into rP k-pair rows
#pragma unroll
            for (int i = 0; i < 8; i++) {
                int f4 = (i&1)*32 + lane;
                int b  = f4 >> 3;
                int jl = (f4 & 7)*4;
                int kp = (wid*4 + (i>>1))*16 + (jl >> 1);
                *(float2*)(rP + (size_t)kp*RPB + b*8)     = make_float2(v[i].x, v[i].y);
                *(float2*)(rP + (size_t)(kp+1)*RPB + b*8) = make_float2(v[i].z, v[i].w);
            }
        }
        __syncwarp();

        // ---- K-loop (monolithic, W in regs)
        ull a0=0,a1=0,a2=0,a3=0,a4=0,a5=0,a6=0,a7=0;
        const char* rb = rP + (size_t)kp0*RPB;
#pragma unroll
        for (int u = 0; u < 64; u++) {
            const ulonglong2* rp = (const ulonglong2*)(rb + u*RPB);
            ulonglong2 q0 = rp[0], q1 = rp[1], q2 = rp[2], q3 = rp[3];
            ull w = w2[u];
            fma2(a0, w, q0.x); fma2(a1, w, q0.y);
            fma2(a2, w, q1.x); fma2(a3, w, q1.y);
            fma2(a4, w, q2.x); fma2(a5, w, q2.y);
            fma2(a6, w, q3.x); fma2(a7, w, q3.y);
        }
        float* red = (float*)(redb + (t & 1)*8448);
        red[(wid*8+0)*33+lane] = hsum2(a0); red[(wid*8+1)*33+lane] = hsum2(a1);
        red[(wid*8+2)*33+lane] = hsum2(a2); red[(wid*8+3)*33+lane] = hsum2(a3);
        red[(wid*8+4)*33+lane] = hsum2(a4); red[(wid*8+5)*33+lane] = hsum2(a5);
        red[(wid*8+6)*33+lane] = hsum2(a6); red[(wid*8+7)*33+lane] = hsum2(a7);
        __syncthreads();             // the ONLY sync per step

        {   // ---- epilogue: thread (wid=batch-lane, lane=j)
            float s = preval;
#pragma unroll
            for (int kc = 0; kc < 8; kc++) s += red[(kc*8 + wid)*33 + lane];
            float e = __expf(2.f*fabsf(s));
            float rv = copysignf(1.f - __fdividef(2.f, e + 1.f), s);

            // sentinel-refill slot (t+2)&3 (its readers finished; see proof)
            {
                unsigned* rf = (unsigned*)g_rbuf2 + ((size_t)((t+2)&3))*Bk*Rk + myreg;
                asm volatile("st.relaxed.gpu.global.u32 [%0], %1;"
                             :: "l"(rf), "r"(SENT) : "memory");
            }
            // data store IS the release (orders the refill before it)
            if (t < Sk - 1) {
                float* dp = g_rbuf2 + ((size_t)(t&3))*Bk*Rk + myreg;
                asm volatile("st.release.gpu.global.f32 [%0], %1;"
                             :: "l"(dp), "f"(rv) : "memory");
            }
            // history for out_kernel, off the release path
            g_rs[((size_t)(b0 + wid)*Sk + t)*Rk + (j0 + lane)] = rv;
        }
    }
}

// ---- Phase 3: out = [x, rs] @ W_out^T --------------------------------------
__global__ void __launch_bounds__(256) out_kernel(const float* __restrict__ x,
                                                  const float* __restrict__ Wout,
                                                  float* __restrict__ out)
{
    __shared__ float ws[Ok*1088];
    for (int idx = threadIdx.x; idx < Ok*1088; idx += 256) ws[idx] = Wout[idx];
    __syncthreads();
    int warp = threadIdx.x >> 5, lane = threadIdx.x & 31;
    for (size_t row = (size_t)blockIdx.x*8 + warp; row < (size_t)Bk*Sk;
         row += (size_t)gridDim.x*8) {
        const float* xr = x + row*Ik;
        const float* rr = g_rs + row*Rk;
        float acc[8] = {0,0,0,0,0,0,0,0};
#pragma unroll
        for (int q = 0; q < 2; q++) {
            int k = q*32 + lane; float f = xr[k];
#pragma unroll
            for (int o = 0; o < 8; o++) acc[o] = fmaf(f, ws[o*1088 + k], acc[o]);
        }
#pragma unroll 4
        for (int q = 0; q < 32; q++) {
            int k = q*32 + lane; float f = rr[k];
#pragma unroll
            for (int o = 0; o < 8; o++) acc[o] = fmaf(f, ws[o*1088 + 64 + k], acc[o]);
        }
#pragma unroll
        for (int o = 0; o < 8; o++)
#pragma unroll
            for (int off = 16; off; off >>= 1)
                acc[o] += __shfl_xor_sync(0xffffffffu, acc[o], off);
        if (lane == 0)
#pragma unroll
            for (int o = 0; o < 8; o++) out[row*Ok + o] = acc[o];
    }
}

extern "C" void kernel_launch(void* const* d_in, const int* in_sizes, int n_in,
                              void* d_out, int out_size)
{
    (void)in_sizes; (void)n_in; (void)out_size;
    const float* x    = (const float*)d_in[0];
    const float* Win  = (const float*)d_in[1];
    const float* Wres = (const float*)d_in[2];
    const float* Wout = (const float*)d_in[3];
    cudaFuncSetAttribute(esn_main, cudaFuncAttributeMaxDynamicSharedMemorySize,
                         SMEM_BYTES);
    reset_kernel<<<128, 256>>>();
    pre_kernel<<<(Bk*Sk)/32, 256>>>(x, Win);
    nop_kernel<<<1, 32>>>();    // 2 harness pre-launches + reset + pre + nop
    esn_main<<<NB, 256, SMEM_BYTES>>>(Wres);   // process-launch idx 5 (ncu -s 5)
    out_kernel<<<2048, 256>>>(x, Wout, (float*)d_out);
}